// round 1
// baseline (speedup 1.0000x reference)
#include <cuda_runtime.h>
#include <math.h>

#define BB 8
#define CC 256
#define NN 2048
#define TI 128
#define TJ 128
#define KT 16

__device__ float g_rnorm[BB * NN];
__device__ int   g_idx[BB * NN];

// ---------------------------------------------------------------------------
// Kernel A: reciprocal norms. norm = sqrt(sum_c(x^2) + C*eps)
// ---------------------------------------------------------------------------
__global__ void rnorm_kernel(const float* __restrict__ x) {
    int t = blockIdx.x * blockDim.x + threadIdx.x;
    if (t >= BB * NN) return;
    int b = t / NN, n = t % NN;
    const float* xp = x + (size_t)b * CC * NN + n;
    float s = 0.f;
#pragma unroll 8
    for (int c = 0; c < CC; ++c) {
        float v = xp[(size_t)c * NN];
        s = fmaf(v, v, s);
    }
    s += (float)CC * 1e-6f;
    g_rnorm[t] = rsqrtf(s);
}

// ---------------------------------------------------------------------------
// Kernel B: fused sim GEMM (X^T X per batch) + argmax over j of sim[i,j]*rnorm[j]
// Block: 128 i-rows x full N j-sweep. 256 threads, 8x8 micro-tile.
// ---------------------------------------------------------------------------
__global__ __launch_bounds__(256) void simargmax_kernel(const float* __restrict__ x) {
    int b  = blockIdx.y;
    int i0 = blockIdx.x * TI;
    const float* X = x + (size_t)b * CC * NN;

    __shared__ float As[KT][TI];
    __shared__ float Bs[KT][TJ];
    __shared__ float Rn[TJ];

    int t  = threadIdx.x;
    int tx = t & 15;
    int ty = t >> 4;

    const float NEG_INF = __int_as_float(0xff800000);
    float best[8];
    int   bidx[8];
#pragma unroll
    for (int r = 0; r < 8; ++r) { best[r] = NEG_INF; bidx[r] = 0; }

    for (int jt = 0; jt < NN / TJ; ++jt) {
        int j0 = jt * TJ;
        float acc[8][8];
#pragma unroll
        for (int r = 0; r < 8; ++r)
#pragma unroll
            for (int c = 0; c < 8; ++c) acc[r][c] = 0.f;

        for (int k0 = 0; k0 < CC; k0 += KT) {
            __syncthreads();  // protect previous tile reads
#pragma unroll
            for (int e = t; e < KT * TI; e += 256) {
                int k = e >> 7;
                int m = e & 127;
                As[k][m] = X[(size_t)(k0 + k) * NN + i0 + m];
                Bs[k][m] = X[(size_t)(k0 + k) * NN + j0 + m];
            }
            if (k0 == 0 && t < TJ) Rn[t] = g_rnorm[b * NN + j0 + t];
            __syncthreads();

#pragma unroll
            for (int k = 0; k < KT; ++k) {
                float a[8], bv[8];
#pragma unroll
                for (int r = 0; r < 8; ++r) a[r]  = As[k][ty + r * 16];
#pragma unroll
                for (int c = 0; c < 8; ++c) bv[c] = Bs[k][tx + c * 16];
#pragma unroll
                for (int r = 0; r < 8; ++r)
#pragma unroll
                    for (int c = 0; c < 8; ++c)
                        acc[r][c] = fmaf(a[r], bv[c], acc[r][c]);
            }
        }

        // epilogue: scale by rnorm[j], mask diagonal, running argmax
        // j increases monotonically across (jt, c) for fixed tx -> '>' keeps first index
#pragma unroll
        for (int c = 0; c < 8; ++c) {
            int j = j0 + tx + c * 16;
            float rn = Rn[tx + c * 16];
#pragma unroll
            for (int r = 0; r < 8; ++r) {
                int i = i0 + ty + r * 16;
                float v = acc[r][c] * rn;
                if (j == i) v = NEG_INF;
                if (v > best[r]) { best[r] = v; bidx[r] = j; }
            }
        }
    }

    // reduce across the 16 tx-threads sharing each row (they sit in 16-lane groups)
#pragma unroll
    for (int r = 0; r < 8; ++r) {
        float v = best[r];
        int   j = bidx[r];
#pragma unroll
        for (int o = 8; o > 0; o >>= 1) {
            float vo = __shfl_xor_sync(0xffffffffu, v, o, 16);
            int   jo = __shfl_xor_sync(0xffffffffu, j, o, 16);
            if (vo > v || (vo == v && jo < j)) { v = vo; j = jo; }
        }
        if (tx == 0) g_idx[b * NN + i0 + ty + r * 16] = j;
    }
}

// ---------------------------------------------------------------------------
// Kernel C: gather f_re, gated fusion, write out (offset 0) and f_re (offset B*C*N)
// ---------------------------------------------------------------------------
__global__ __launch_bounds__(128) void fuse_kernel(const float* __restrict__ x,
                                                   const float* __restrict__ W,
                                                   float* __restrict__ out) {
    __shared__ float Ws[4 * CC];  // [2][2C] row-major
    int b = blockIdx.y;
    int n = blockIdx.x * 128 + threadIdx.x;
    for (int e = threadIdx.x; e < 4 * CC; e += 128) Ws[e] = W[e];
    __syncthreads();

    const float* xb = x + (size_t)b * CC * NN;
    int j = g_idx[b * NN + n];

    float l0 = 0.f, l1 = 0.f;
#pragma unroll 4
    for (int c = 0; c < CC; ++c) {
        float xv = xb[(size_t)c * NN + n];
        float fv = xb[(size_t)c * NN + j];
        l0 = fmaf(xv, Ws[c], l0);
        l0 = fmaf(fv, Ws[CC + c], l0);
        l1 = fmaf(xv, Ws[2 * CC + c], l1);
        l1 = fmaf(fv, Ws[3 * CC + c], l1);
    }
    float m  = fmaxf(l0, l1);
    float e0 = expf(l0 - m), e1 = expf(l1 - m);
    float inv = 1.f / (e0 + e1);
    float w0 = e0 * inv, w1 = e1 * inv;

    float* o0 = out + (size_t)b * CC * NN;
    float* o1 = out + (size_t)BB * CC * NN + (size_t)b * CC * NN;
#pragma unroll 4
    for (int c = 0; c < CC; ++c) {
        float xv = xb[(size_t)c * NN + n];
        float fv = xb[(size_t)c * NN + j];
        o0[(size_t)c * NN + n] = fmaf(xv, w0, fv * w1);
        o1[(size_t)c * NN + n] = fv;
    }
}

// ---------------------------------------------------------------------------
extern "C" void kernel_launch(void* const* d_in, const int* in_sizes, int n_in,
                              void* d_out, int out_size) {
    const float* x = (const float*)d_in[0];
    const float* W = (const float*)d_in[1];
    float* out = (float*)d_out;

    rnorm_kernel<<<(BB * NN + 255) / 256, 256>>>(x);

    dim3 gb(NN / TI, BB);
    simargmax_kernel<<<gb, 256>>>(x);

    dim3 gc(NN / 128, BB);
    fuse_kernel<<<gc, 128>>>(x, W, out);
}

// round 2
// speedup vs baseline: 1.5581x; 1.5581x over previous
#include <cuda_runtime.h>
#include <cuda_bf16.h>
#include <math.h>
#include <stdint.h>

#define BB 8
#define CC 256
#define NN 2048

// 3 bf16 splits, K-contiguous rows: g_xs[b][n][s*256 + c]
__device__ __align__(16) __nv_bfloat16 g_xs[(size_t)BB * NN * 768];
__device__ float g_rnorm[BB * NN];
__device__ int   g_idx[BB * NN];

// ---------------------------------------------------------------------------
// prep: transpose + 3-way bf16 split + rnorm
// grid (NN/32, BB), block 256. thread = (n_local = tid&31, c8 = tid>>5)
// ---------------------------------------------------------------------------
__global__ __launch_bounds__(256) void prep_kernel(const float* __restrict__ x) {
    __shared__ __nv_bfloat16 S[32][776];   // 776 = 768 + 8 pad (keeps 16B align)
    __shared__ float nsum[32][8];
    int b = blockIdx.y, n0 = blockIdx.x * 32;
    int tid = threadIdx.x;
    int nl = tid & 31, c8 = tid >> 5;
    const float* xp = x + (size_t)b * CC * NN + n0 + nl;
    float s = 0.f;
#pragma unroll
    for (int cc = 0; cc < 32; ++cc) {
        int c = c8 * 32 + cc;
        float v = xp[(size_t)c * NN];
        __nv_bfloat16 h1 = __float2bfloat16(v);
        float r1 = v - __bfloat162float(h1);
        __nv_bfloat16 h2 = __float2bfloat16(r1);
        float r2 = r1 - __bfloat162float(h2);
        __nv_bfloat16 h3 = __float2bfloat16(r2);
        S[nl][c] = h1; S[nl][256 + c] = h2; S[nl][512 + c] = h3;
        s = fmaf(v, v, s);
    }
    nsum[nl][c8] = s;
    __syncthreads();
    if (tid < 32) {
        float t = 0.f;
#pragma unroll
        for (int q = 0; q < 8; ++q) t += nsum[tid][q];
        g_rnorm[b * NN + n0 + tid] = rsqrtf(t + (float)CC * 1e-6f);
    }
    __nv_bfloat16* outb = g_xs + ((size_t)b * NN + n0) * 768;
#pragma unroll
    for (int r = 0; r < 12; ++r) {
        int idx = tid + r * 256;          // 32 rows x 96 uint4
        int row = idx / 96, c16 = idx % 96;
        uint4 v = *(const uint4*)&S[row][c16 * 8];
        *(uint4*)(outb + (size_t)row * 768 + c16 * 8) = v;
    }
}

// ---------------------------------------------------------------------------
// smem layout for the GEMM kernel (byte offsets; 16B chunk granularity)
// ---------------------------------------------------------------------------
#define ARES_BYTES (2 * 128 * 33 * 16)          // resident A splits 0,1; row stride 33 chunks (pad)
#define BOFF       (ARES_BYTES)
#define BBUF_BYTES (2 * 128 * 9 * 16)           // B double buffer; row stride 9 chunks
#define STOFF      (BOFF + BBUF_BYTES)          // streamed A (split 2) double buffer
#define STBYTES    (2 * 128 * 9 * 16)
#define RNOFF      (STOFF + STBYTES)
#define RVOFF      (RNOFF + 512)
#define RJOFF      (RVOFF + 512)
#define SMEM_TOTAL (RJOFF + 512)                // 210,944 B

__device__ __forceinline__ void ldsm4(uint32_t* r, uint32_t saddr) {
    asm volatile("ldmatrix.sync.aligned.m8n8.x4.shared.b16 {%0,%1,%2,%3}, [%4];"
                 : "=r"(r[0]), "=r"(r[1]), "=r"(r[2]), "=r"(r[3]) : "r"(saddr));
}
__device__ __forceinline__ void mma16816(float (&d)[4], const uint32_t (&a)[4],
                                         uint32_t b0, uint32_t b1) {
    asm volatile(
        "mma.sync.aligned.m16n8k16.row.col.f32.bf16.bf16.f32 "
        "{%0,%1,%2,%3},{%4,%5,%6,%7},{%8,%9},{%0,%1,%2,%3};"
        : "+f"(d[0]), "+f"(d[1]), "+f"(d[2]), "+f"(d[3])
        : "r"(a[0]), "r"(a[1]), "r"(a[2]), "r"(a[3]), "r"(b0), "r"(b1));
}

__device__ __forceinline__ void loadB_regs(uint4* r, const __nv_bfloat16* xsb,
                                           int j0, int sb, int kc, int tid) {
#pragma unroll
    for (int q = 0; q < 4; ++q) {
        int idx = tid + q * 256;
        int row = idx >> 3, ch = idx & 7;
        r[q] = *(const uint4*)(xsb + (size_t)(j0 + row) * 768 + sb * 256 + kc * 64 + ch * 8);
    }
}
__device__ __forceinline__ void storeB_smem(char* sm, const uint4* r, int buf, int tid) {
#pragma unroll
    for (int q = 0; q < 4; ++q) {
        int idx = tid + q * 256;
        int row = idx >> 3, ch = idx & 7;
        *(uint4*)(sm + BOFF + ((((buf << 7) + row) * 9 + ch) << 4)) = r[q];
    }
}
__device__ __forceinline__ void loadAst_regs(uint4* r, const __nv_bfloat16* xsb,
                                             int i0, int kc, int tid) {
#pragma unroll
    for (int q = 0; q < 4; ++q) {
        int idx = tid + q * 256;
        int row = idx >> 3, ch = idx & 7;
        r[q] = *(const uint4*)(xsb + (size_t)(i0 + row) * 768 + 512 + kc * 64 + ch * 8);
    }
}
__device__ __forceinline__ void storeAst_smem(char* sm, const uint4* r, int buf, int tid) {
#pragma unroll
    for (int q = 0; q < 4; ++q) {
        int idx = tid + q * 256;
        int row = idx >> 3, ch = idx & 7;
        *(uint4*)(sm + STOFF + ((((buf << 7) + row) * 9 + ch) << 4)) = r[q];
    }
}

// ---------------------------------------------------------------------------
// simargmax: emulated-fp32 GEMM via 6 bf16 split-pair MMAs + fused argmax
// grid (16, BB), 256 threads = 8 warps (4 M x 2 N), CTA tile 128x128
// ---------------------------------------------------------------------------
__global__ __launch_bounds__(256, 1) void simargmax_kernel() {
    extern __shared__ char sm[];
    const int b = blockIdx.y, i0 = blockIdx.x * 128;
    const int tid = threadIdx.x, lane = tid & 31, wid = tid >> 5;
    const int wm = wid >> 1, wn = wid & 1;
    const uint32_t smb = (uint32_t)__cvta_generic_to_shared(sm);
    const __nv_bfloat16* xsb = g_xs + (size_t)b * NN * 768;
    float* Rn = (float*)(sm + RNOFF);

    // pair table: (sa, sb) for {11,12,21,22,13,31}; pair 5 streams A-split-2
    const int PSA[6] = {0, 0, 1, 1, 0, 2};
    const int PSB[6] = {0, 1, 0, 1, 2, 0};

    // resident A: splits 0,1 for rows i0..i0+127, full K=256
#pragma unroll
    for (int r = 0; r < 32; ++r) {
        int idx = tid + r * 256;            // 8192 chunks total
        int s   = idx >> 12;
        int row = (idx >> 5) & 127;
        int ch  = idx & 31;
        uint4 v = *(const uint4*)(xsb + (size_t)(i0 + row) * 768 + s * 256 + ch * 8);
        *(uint4*)(sm + ((((s << 7) + row) * 33 + ch) << 4)) = v;
    }

    const int ar0 = wm * 32 + (lane & 15);          // A ldmatrix row (+ mt*16)
    const int akh = lane >> 4;                      // A k-half chunk
    const int jr0 = wn * 64 + ((lane >> 4) & 1) * 8 + (lane & 7);  // B row (+ ntp*16)
    const int bkh = (lane >> 3) & 1;                // B k-half chunk

    const float NEG = __int_as_float(0xff800000);
    float best[4]; int bidx[4];
#pragma unroll
    for (int s = 0; s < 4; ++s) { best[s] = NEG; bidx[s] = 0; }

    for (int jt = 0; jt < 16; ++jt) {
        const int j0 = jt * 128;
        if (tid < 128) Rn[tid] = g_rnorm[b * NN + j0 + tid];

        float acc[2][8][4];
#pragma unroll
        for (int mt = 0; mt < 2; ++mt)
#pragma unroll
            for (int nt = 0; nt < 8; ++nt)
#pragma unroll
                for (int rr = 0; rr < 4; ++rr) acc[mt][nt][rr] = 0.f;

        uint4 breg[4], areg[4];
        loadB_regs(breg, xsb, j0, PSB[0], 0, tid);
        storeB_smem(sm, breg, 0, tid);
        __syncthreads();

        for (int it = 0; it < 24; ++it) {
            const int buf = it & 1;
            const int p = it >> 2, kc = it & 3;
            const int itn = it + 1;
            const bool hn = itn < 24;
            const int pn = itn >> 2, kcn = itn & 3;
            if (hn) {
                loadB_regs(breg, xsb, j0, PSB[pn], kcn, tid);
                if (pn == 5) loadAst_regs(areg, xsb, i0, kcn, tid);
            }
            // compute chunk it (K = 64 = 4 k-steps of 16)
#pragma unroll
            for (int ks = 0; ks < 4; ++ks) {
                uint32_t a[2][4];
                if (p < 5) {
                    const int sa = PSA[p];
                    const int cb = kc * 8 + ks * 2;
#pragma unroll
                    for (int mt = 0; mt < 2; ++mt) {
                        uint32_t ad = smb + (((((sa << 7) + ar0 + mt * 16) * 33) + cb + akh) << 4);
                        ldsm4(a[mt], ad);
                    }
                } else {
                    const int cbs = ks * 2;
#pragma unroll
                    for (int mt = 0; mt < 2; ++mt) {
                        uint32_t ad = smb + STOFF +
                            (((((buf << 7) + ar0 + mt * 16) * 9) + cbs + akh) << 4);
                        ldsm4(a[mt], ad);
                    }
                }
#pragma unroll
                for (int ntp = 0; ntp < 4; ++ntp) {
                    uint32_t bf[4];
                    uint32_t bd = smb + BOFF +
                        (((((buf << 7) + jr0 + ntp * 16) * 9) + ks * 2 + bkh) << 4);
                    ldsm4(bf, bd);
                    mma16816(acc[0][ntp * 2],     a[0], bf[0], bf[1]);
                    mma16816(acc[0][ntp * 2 + 1], a[0], bf[2], bf[3]);
                    mma16816(acc[1][ntp * 2],     a[1], bf[0], bf[1]);
                    mma16816(acc[1][ntp * 2 + 1], a[1], bf[2], bf[3]);
                }
            }
            if (hn) {
                storeB_smem(sm, breg, buf ^ 1, tid);
                if (pn == 5) storeAst_smem(sm, areg, buf ^ 1, tid);
            }
            __syncthreads();
        }

        // epilogue: scale by rnorm[j], mask diagonal, running argmax
#pragma unroll
        for (int mt = 0; mt < 2; ++mt)
#pragma unroll
            for (int nt = 0; nt < 8; ++nt)
#pragma unroll
                for (int rr = 0; rr < 4; ++rr) {
                    int jl = wn * 64 + nt * 8 + (lane & 3) * 2 + (rr & 1);
                    int il = wm * 32 + mt * 16 + (rr >> 1) * 8 + (lane >> 2);
                    float v = acc[mt][nt][rr] * Rn[jl];
                    if (j0 + jl == i0 + il) v = NEG;
                    int slot = mt * 2 + (rr >> 1);
                    if (v > best[slot]) { best[slot] = v; bidx[slot] = j0 + jl; }
                }
        __syncthreads();   // protect Rn before next j-tile overwrites it
    }

    // cross-lane (quad) + cross-warp_n reduction; first-index tie-break
    float* Rv = (float*)(sm + RVOFF);
    int*   Rj = (int*)(sm + RJOFF);
#pragma unroll
    for (int slot = 0; slot < 4; ++slot) {
        float v = best[slot]; int j = bidx[slot];
#pragma unroll
        for (int o = 1; o <= 2; o <<= 1) {
            float vo = __shfl_xor_sync(0xffffffffu, v, o);
            int   jo = __shfl_xor_sync(0xffffffffu, j, o);
            if (vo > v || (vo == v && jo < j)) { v = vo; j = jo; }
        }
        best[slot] = v; bidx[slot] = j;
        int row = wm * 32 + (slot >> 1) * 16 + (slot & 1) * 8 + (lane >> 2);
        if (wn == 1 && (lane & 3) == 0) { Rv[row] = v; Rj[row] = j; }
    }
    __syncthreads();
    if (wn == 0 && (lane & 3) == 0) {
#pragma unroll
        for (int slot = 0; slot < 4; ++slot) {
            int row = wm * 32 + (slot >> 1) * 16 + (slot & 1) * 8 + (lane >> 2);
            float v = best[slot]; int j = bidx[slot];
            float vo = Rv[row]; int jo = Rj[row];
            if (vo > v || (vo == v && jo < j)) { v = vo; j = jo; }
            g_idx[b * NN + i0 + row] = j;
        }
    }
}

// ---------------------------------------------------------------------------
// fuse: gather f_re, 2-way softmax gate, write out + f_re
// ---------------------------------------------------------------------------
__global__ __launch_bounds__(128) void fuse_kernel(const float* __restrict__ x,
                                                   const float* __restrict__ W,
                                                   float* __restrict__ out) {
    __shared__ float Ws[4 * CC];
    int b = blockIdx.y;
    int n = blockIdx.x * 128 + threadIdx.x;
    for (int e = threadIdx.x; e < 4 * CC; e += 128) Ws[e] = W[e];
    __syncthreads();

    const float* xb = x + (size_t)b * CC * NN;
    int j = g_idx[b * NN + n];

    float l0 = 0.f, l1 = 0.f;
#pragma unroll 4
    for (int c = 0; c < CC; ++c) {
        float xv = xb[(size_t)c * NN + n];
        float fv = xb[(size_t)c * NN + j];
        l0 = fmaf(xv, Ws[c], l0);
        l0 = fmaf(fv, Ws[CC + c], l0);
        l1 = fmaf(xv, Ws[2 * CC + c], l1);
        l1 = fmaf(fv, Ws[3 * CC + c], l1);
    }
    float m  = fmaxf(l0, l1);
    float e0 = expf(l0 - m), e1 = expf(l1 - m);
    float inv = 1.f / (e0 + e1);
    float w0 = e0 * inv, w1 = e1 * inv;

    float* o0 = out + (size_t)b * CC * NN;
    float* o1 = out + (size_t)BB * CC * NN + (size_t)b * CC * NN;
#pragma unroll 4
    for (int c = 0; c < CC; ++c) {
        float xv = xb[(size_t)c * NN + n];
        float fv = xb[(size_t)c * NN + j];
        o0[(size_t)c * NN + n] = fmaf(xv, w0, fv * w1);
        o1[(size_t)c * NN + n] = fv;
    }
}

// ---------------------------------------------------------------------------
extern "C" void kernel_launch(void* const* d_in, const int* in_sizes, int n_in,
                              void* d_out, int out_size) {
    const float* x = (const float*)d_in[0];
    const float* W = (const float*)d_in[1];
    float* out = (float*)d_out;

    cudaFuncSetAttribute(simargmax_kernel,
                         cudaFuncAttributeMaxDynamicSharedMemorySize, SMEM_TOTAL);

    prep_kernel<<<dim3(NN / 32, BB), 256>>>(x);
    simargmax_kernel<<<dim3(16, BB), 256, SMEM_TOTAL>>>();
    fuse_kernel<<<dim3(NN / 128, BB), 128>>>(x, W, out);
}

// round 4
// speedup vs baseline: 2.6507x; 1.7012x over previous
#include <cuda_runtime.h>
#include <cuda_fp16.h>
#include <math.h>
#include <stdint.h>

#define BB 8
#define CC 256
#define NN 2048

// rn-scaled 2-way fp16 splits, K-contiguous: g_xs[b][n][s*256 + c], s in {0,1}
__device__ __align__(16) __half g_xs[(size_t)BB * NN * 512];
// transposed f32 copy for fuse gathers: g_xt[b][n][c]
__device__ __align__(16) float g_xt[(size_t)BB * NN * CC];
__device__ int g_idx[BB * NN];

// ---------------------------------------------------------------------------
// prep: per token compute rn, write f32 transpose (g_xt) and rn-scaled 2-way
// fp16 splits (g_xs). grid (NN/32, BB), 256 threads.
// ---------------------------------------------------------------------------
__global__ __launch_bounds__(256) void prep_kernel(const float* __restrict__ x) {
    __shared__ __half S[32][520];       // 512 + 8 pad
    __shared__ float nsum[32][8];
    __shared__ float rns[32];
    int b = blockIdx.y, n0 = blockIdx.x * 32;
    int tid = threadIdx.x, nl = tid & 31, c8 = tid >> 5;
    const float* xp = x + (size_t)b * CC * NN + n0 + nl;

    float v[32];
    float s = 0.f;
#pragma unroll
    for (int cc = 0; cc < 32; ++cc) {
        int c = c8 * 32 + cc;
        v[cc] = xp[(size_t)c * NN];
        s = fmaf(v[cc], v[cc], s);
    }
    nsum[nl][c8] = s;
    __syncthreads();
    if (tid < 32) {
        float t = 0.f;
#pragma unroll
        for (int q = 0; q < 8; ++q) t += nsum[tid][q];
        rns[tid] = rsqrtf(t + (float)CC * 1e-6f);
    }
    __syncthreads();
    float rn = rns[nl];

    float* xt = g_xt + ((size_t)(b * NN + n0 + nl)) * 256 + c8 * 32;
#pragma unroll
    for (int q = 0; q < 8; ++q)
        *(float4*)(xt + q * 4) = make_float4(v[q * 4], v[q * 4 + 1], v[q * 4 + 2], v[q * 4 + 3]);

#pragma unroll
    for (int cc = 0; cc < 32; ++cc) {
        int c = c8 * 32 + cc;
        float f = v[cc] * rn;
        __half h1 = __float2half_rn(f);
        float r1 = f - __half2float(h1);
        __half h2 = __float2half_rn(r1);
        S[nl][c] = h1; S[nl][256 + c] = h2;
    }
    __syncthreads();

    __half* outb = g_xs + ((size_t)(b * NN + n0)) * 512;
#pragma unroll
    for (int r = 0; r < 8; ++r) {
        int idx = tid + r * 256;          // 32 rows x 64 uint4
        int row = idx >> 6, c16 = idx & 63;
        uint4 val = *(const uint4*)&S[row][c16 * 8];
        *(uint4*)(outb + (size_t)row * 512 + c16 * 8) = val;
    }
}

// ---------------------------------------------------------------------------
// smem map for simargmax (byte offsets; 16B chunk granularity)
// ---------------------------------------------------------------------------
#define ARES_BYTES (2 * 128 * 33 * 16)          // resident A splits 0,1; padded stride 33 chunks
#define BOFF       (ARES_BYTES)                 // 135168
#define BBUF_BYTES (2 * 128 * 9 * 16)           // B double buffer; padded stride 9 chunks
#define MVOFF      (BOFF + BBUF_BYTES)          // 172032: merge values 128 f32
#define MJOFF      (MVOFF + 512)
#define SMEM_TOTAL (MJOFF + 512)                // 173056

__device__ __forceinline__ void ldsm4(uint32_t* r, uint32_t saddr) {
    asm volatile("ldmatrix.sync.aligned.m8n8.x4.shared.b16 {%0,%1,%2,%3}, [%4];"
                 : "=r"(r[0]), "=r"(r[1]), "=r"(r[2]), "=r"(r[3]) : "r"(saddr));
}
__device__ __forceinline__ void mma16816(float (&d)[4], const uint32_t (&a)[4],
                                         uint32_t b0, uint32_t b1) {
    asm volatile(
        "mma.sync.aligned.m16n8k16.row.col.f32.f16.f16.f32 "
        "{%0,%1,%2,%3},{%4,%5,%6,%7},{%8,%9},{%0,%1,%2,%3};"
        : "+f"(d[0]), "+f"(d[1]), "+f"(d[2]), "+f"(d[3])
        : "r"(a[0]), "r"(a[1]), "r"(a[2]), "r"(a[3]), "r"(b0), "r"(b1));
}

__device__ __forceinline__ void loadB_regs(uint4* r, const __half* xsb,
                                           int j0, int sb, int kc, int tid) {
#pragma unroll
    for (int q = 0; q < 4; ++q) {
        int idx = tid + q * 256;
        int row = idx >> 3, ch = idx & 7;
        r[q] = *(const uint4*)(xsb + (size_t)(j0 + row) * 512 + sb * 256 + kc * 64 + ch * 8);
    }
}
__device__ __forceinline__ void storeB_smem(char* sm, const uint4* r, int buf, int tid) {
#pragma unroll
    for (int q = 0; q < 4; ++q) {
        int idx = tid + q * 256;
        int row = idx >> 3, ch = idx & 7;
        *(uint4*)(sm + BOFF + ((((buf << 7) + row) * 9 + ch) << 4)) = r[q];
    }
}

// ---------------------------------------------------------------------------
// simargmax: emulated-fp32 GEMM via 4 fp16 split-pair MMAs + fused argmax.
// grid (16, BB), 256 threads = 8 warps (4 M x 2 N), CTA tile 128x128.
// ---------------------------------------------------------------------------
__global__ __launch_bounds__(256, 1) void simargmax_kernel() {
    extern __shared__ __align__(1024) char sm[];
    const int b = blockIdx.y, i0 = blockIdx.x * 128;
    const int tid = threadIdx.x, lane = tid & 31, wid = tid >> 5;
    const int wm = wid >> 1, wn = wid & 1;
    const uint32_t smb = (uint32_t)__cvta_generic_to_shared(sm);
    const __half* xsb = g_xs + (size_t)b * NN * 512;

    // resident A: both splits, rows i0..i0+127, full K=256 (32 chunks/row)
#pragma unroll
    for (int r = 0; r < 32; ++r) {
        int idx = tid + r * 256;            // 8192 chunks
        int s   = idx >> 12;
        int row = (idx >> 5) & 127;
        int ch  = idx & 31;
        uint4 v = *(const uint4*)(xsb + (size_t)(i0 + row) * 512 + s * 256 + ch * 8);
        *(uint4*)(sm + ((((s << 7) + row) * 33 + ch) << 4)) = v;
    }

    const int ar0 = wm * 32 + (lane & 15);          // A ldmatrix row (+ mt*16)
    const int akh = lane >> 4;                      // A k-half chunk
    const int jr0 = wn * 64 + ((lane >> 4) & 1) * 8 + (lane & 7);  // B row (+ ntp*16)
    const int bkh = (lane >> 3) & 1;                // B k-half chunk

    const float NEG = __int_as_float(0xff800000);
    float best[4]; int bidx[4];
#pragma unroll
    for (int s = 0; s < 4; ++s) { best[s] = NEG; bidx[s] = 0; }

    for (int jt = 0; jt < 16; ++jt) {
        const int j0 = jt * 128;
        float acc[2][8][4];
#pragma unroll
        for (int mt = 0; mt < 2; ++mt)
#pragma unroll
            for (int nt = 0; nt < 8; ++nt)
#pragma unroll
                for (int rr = 0; rr < 4; ++rr) acc[mt][nt][rr] = 0.f;

        uint4 breg[4];
        loadB_regs(breg, xsb, j0, 0, 0, tid);
        __syncthreads();              // previous jt fully done reading B bufs
        storeB_smem(sm, breg, 0, tid);
        __syncthreads();

        // 8 B tiles per jt: (sb, kc); each consumed by both A splits
        for (int it = 0; it < 8; ++it) {
            const int buf = it & 1;
            const int kc = it & 3;
            const int itn = it + 1;
            const bool hn = itn < 8;
            if (hn) loadB_regs(breg, xsb, j0, itn >> 2, itn & 3, tid);

#pragma unroll
            for (int ks = 0; ks < 4; ++ks) {
                // B fragments for this k-step (shared across both A splits)
                uint32_t bf[4][4];
#pragma unroll
                for (int ntp = 0; ntp < 4; ++ntp) {
                    uint32_t bd = smb + BOFF +
                        (((((buf << 7) + jr0 + ntp * 16) * 9) + ks * 2 + bkh) << 4);
                    ldsm4(bf[ntp], bd);
                }
#pragma unroll
                for (int q = 0; q < 2; ++q) {
                    uint32_t a[2][4];
                    const int cb = kc * 8 + ks * 2;
#pragma unroll
                    for (int mt = 0; mt < 2; ++mt) {
                        uint32_t ad = smb + (((((q << 7) + ar0 + mt * 16) * 33) + cb + akh) << 4);
                        ldsm4(a[mt], ad);
                    }
#pragma unroll
                    for (int ntp = 0; ntp < 4; ++ntp) {
                        mma16816(acc[0][ntp * 2],     a[0], bf[ntp][0], bf[ntp][1]);
                        mma16816(acc[0][ntp * 2 + 1], a[0], bf[ntp][2], bf[ntp][3]);
                        mma16816(acc[1][ntp * 2],     a[1], bf[ntp][0], bf[ntp][1]);
                        mma16816(acc[1][ntp * 2 + 1], a[1], bf[ntp][2], bf[ntp][3]);
                    }
                }
            }
            __syncthreads();
            if (hn) {
                storeB_smem(sm, breg, buf ^ 1, tid);
                __syncthreads();
            }
        }

        // epilogue: mask diagonal, running argmax (j monotonic -> '>' keeps first)
#pragma unroll
        for (int mt = 0; mt < 2; ++mt)
#pragma unroll
            for (int nt = 0; nt < 8; ++nt)
#pragma unroll
                for (int rr = 0; rr < 4; ++rr) {
                    int jl = wn * 64 + nt * 8 + (lane & 3) * 2 + (rr & 1);
                    int il = wm * 32 + mt * 16 + (rr >> 1) * 8 + (lane >> 2);
                    float v = acc[mt][nt][rr];
                    if (j0 + jl == i0 + il) v = NEG;
                    int slot = mt * 2 + (rr >> 1);
                    if (v > best[slot]) { best[slot] = v; bidx[slot] = j0 + jl; }
                }
    }

    // cross-lane (quad) + cross-warp_n reduction; first-index tie-break
    float* Rv = (float*)(sm + MVOFF);
    int*   Rj = (int*)(sm + MJOFF);
#pragma unroll
    for (int slot = 0; slot < 4; ++slot) {
        float v = best[slot]; int j = bidx[slot];
#pragma unroll
        for (int o = 1; o <= 2; o <<= 1) {
            float vo = __shfl_xor_sync(0xffffffffu, v, o);
            int   jo = __shfl_xor_sync(0xffffffffu, j, o);
            if (vo > v || (vo == v && jo < j)) { v = vo; j = jo; }
        }
        best[slot] = v; bidx[slot] = j;
        int row = wm * 32 + (slot >> 1) * 16 + (slot & 1) * 8 + (lane >> 2);
        if (wn == 1 && (lane & 3) == 0) { Rv[row] = v; Rj[row] = j; }
    }
    __syncthreads();
    if (wn == 0 && (lane & 3) == 0) {
#pragma unroll
        for (int slot = 0; slot < 4; ++slot) {
            int row = wm * 32 + (slot >> 1) * 16 + (slot & 1) * 8 + (lane >> 2);
            float v = best[slot]; int j = bidx[slot];
            float vo = Rv[row]; int jo = Rj[row];
            if (vo > v || (vo == v && jo < j)) { v = vo; j = jo; }
            g_idx[b * NN + i0 + row] = j;
        }
    }
}

// ---------------------------------------------------------------------------
// fuse: staged in smem via g_xt; coalesced reads/writes. grid (NN/32, BB), 256 thr.
// ---------------------------------------------------------------------------
#define FS_SF 32896
#define FS_W  65792
#define FS_JI 69888
#define FS_W0 70016
#define FS_W1 70144
#define FS_TOTAL 70272

__global__ __launch_bounds__(256) void fuse_kernel(const float* __restrict__ W,
                                                   float* __restrict__ out) {
    extern __shared__ char fsm[];
    float* Sx  = (float*)fsm;               // [32][257]
    float* Sf  = (float*)(fsm + FS_SF);     // [32][257]
    float* Wsh = (float*)(fsm + FS_W);      // [1024]
    int*   Ji  = (int*)(fsm + FS_JI);
    float* W0  = (float*)(fsm + FS_W0);
    float* W1  = (float*)(fsm + FS_W1);

    int b = blockIdx.y, n0 = blockIdx.x * 32, tid = threadIdx.x;
    for (int e = tid; e < 1024; e += 256) Wsh[e] = W[e];
    if (tid < 32) Ji[tid] = g_idx[b * NN + n0 + tid];
    __syncthreads();

    const float* xtb = g_xt + (size_t)b * NN * 256;
    {
        int r = tid >> 3, p = tid & 7;
        const float* srcx = xtb + (size_t)(n0 + r) * 256 + p * 32;
        const float* srcf = xtb + (size_t)Ji[r] * 256 + p * 32;
#pragma unroll
        for (int q = 0; q < 8; ++q) {
            float4 a = *(const float4*)(srcx + q * 4);
            float4 c = *(const float4*)(srcf + q * 4);
            int cb = p * 32 + q * 4;
            Sx[r * 257 + cb] = a.x; Sx[r * 257 + cb + 1] = a.y;
            Sx[r * 257 + cb + 2] = a.z; Sx[r * 257 + cb + 3] = a.w;
            Sf[r * 257 + cb] = c.x; Sf[r * 257 + cb + 1] = c.y;
            Sf[r * 257 + cb + 2] = c.z; Sf[r * 257 + cb + 3] = c.w;
        }
    }
    __syncthreads();
    {
        int r = tid >> 3, p = tid & 7;
        float l0 = 0.f, l1 = 0.f;
#pragma unroll
        for (int cc = 0; cc < 32; ++cc) {
            int c = p * 32 + cc;
            float xv = Sx[r * 257 + c], fv = Sf[r * 257 + c];
            l0 = fmaf(xv, Wsh[c], fmaf(fv, Wsh[256 + c], l0));
            l1 = fmaf(xv, Wsh[512 + c], fmaf(fv, Wsh[768 + c], l1));
        }
#pragma unroll
        for (int o = 4; o; o >>= 1) {
            l0 += __shfl_down_sync(0xffffffffu, l0, o, 8);
            l1 += __shfl_down_sync(0xffffffffu, l1, o, 8);
        }
        if (p == 0) {
            float m = fmaxf(l0, l1);
            float e0 = expf(l0 - m), e1 = expf(l1 - m);
            float inv = 1.f / (e0 + e1);
            W0[r] = e0 * inv; W1[r] = e1 * inv;
        }
    }
    __syncthreads();
    {
        int nl = tid & 31, cg = tid >> 5;
        float w0 = W0[nl], w1 = W1[nl];
        float* o0 = out + (size_t)b * CC * NN;
        float* o1 = out + (size_t)BB * CC * NN + (size_t)b * CC * NN;
#pragma unroll
        for (int cc = 0; cc < 32; ++cc) {
            int c = cg * 32 + cc;
            float xv = Sx[nl * 257 + c], fv = Sf[nl * 257 + c];
            o0[(size_t)c * NN + n0 + nl] = fmaf(xv, w0, fv * w1);
            o1[(size_t)c * NN + n0 + nl] = fv;
        }
    }
}

// ---------------------------------------------------------------------------
extern "C" void kernel_launch(void* const* d_in, const int* in_sizes, int n_in,
                              void* d_out, int out_size) {
    const float* x = (const float*)d_in[0];
    const float* W = (const float*)d_in[1];
    float* out = (float*)d_out;

    cudaFuncSetAttribute(simargmax_kernel,
                         cudaFuncAttributeMaxDynamicSharedMemorySize, SMEM_TOTAL);
    cudaFuncSetAttribute(fuse_kernel,
                         cudaFuncAttributeMaxDynamicSharedMemorySize, FS_TOTAL);

    prep_kernel<<<dim3(NN / 32, BB), 256>>>(x);
    simargmax_kernel<<<dim3(16, BB), 256, SMEM_TOTAL>>>();
    fuse_kernel<<<dim3(NN / 32, BB), 256, FS_TOTAL>>>(W, out);
}

// round 5
// speedup vs baseline: 2.9929x; 1.1291x over previous
#include <cuda_runtime.h>
#include <cuda_fp16.h>
#include <math.h>
#include <stdint.h>

#define BB 8
#define CC 256
#define NN 2048

// rn-scaled 2-way fp16 splits, K-contiguous: g_xs[b][n][s*256 + c], s in {0,1}
__device__ __align__(16) __half g_xs[(size_t)BB * NN * 512];
// transposed f32 copy for fuse gathers: g_xt[b][n][c]
__device__ __align__(16) float g_xt[(size_t)BB * NN * CC];
__device__ int g_idx[BB * NN];

// ---------------------------------------------------------------------------
// prep: per token compute rn, write f32 transpose (g_xt) and rn-scaled 2-way
// fp16 splits (g_xs). grid (NN/32, BB), 256 threads.
// ---------------------------------------------------------------------------
__global__ __launch_bounds__(256) void prep_kernel(const float* __restrict__ x) {
    __shared__ __half S[32][520];       // 512 + 8 pad
    __shared__ float nsum[32][8];
    __shared__ float rns[32];
    int b = blockIdx.y, n0 = blockIdx.x * 32;
    int tid = threadIdx.x, nl = tid & 31, c8 = tid >> 5;
    const float* xp = x + (size_t)b * CC * NN + n0 + nl;

    float v[32];
    float s = 0.f;
#pragma unroll
    for (int cc = 0; cc < 32; ++cc) {
        int c = c8 * 32 + cc;
        v[cc] = xp[(size_t)c * NN];
        s = fmaf(v[cc], v[cc], s);
    }
    nsum[nl][c8] = s;
    __syncthreads();
    if (tid < 32) {
        float t = 0.f;
#pragma unroll
        for (int q = 0; q < 8; ++q) t += nsum[tid][q];
        rns[tid] = rsqrtf(t + (float)CC * 1e-6f);
    }
    __syncthreads();
    float rn = rns[nl];

    float* xt = g_xt + ((size_t)(b * NN + n0 + nl)) * 256 + c8 * 32;
#pragma unroll
    for (int q = 0; q < 8; ++q)
        *(float4*)(xt + q * 4) = make_float4(v[q * 4], v[q * 4 + 1], v[q * 4 + 2], v[q * 4 + 3]);

#pragma unroll
    for (int cc = 0; cc < 32; ++cc) {
        int c = c8 * 32 + cc;
        float f = v[cc] * rn;
        __half h1 = __float2half_rn(f);
        float r1 = f - __half2float(h1);
        __half h2 = __float2half_rn(r1);
        S[nl][c] = h1; S[nl][256 + c] = h2;
    }
    __syncthreads();

    __half* outb = g_xs + ((size_t)(b * NN + n0)) * 512;
#pragma unroll
    for (int r = 0; r < 8; ++r) {
        int idx = tid + r * 256;          // 32 rows x 64 uint4
        int row = idx >> 6, c16 = idx & 63;
        uint4 val = *(const uint4*)&S[row][c16 * 8];
        *(uint4*)(outb + (size_t)row * 512 + c16 * 8) = val;
    }
}

// ---------------------------------------------------------------------------
// smem map for simargmax (byte offsets; 16B chunk granularity)
// ---------------------------------------------------------------------------
#define ARES_BYTES (2 * 128 * 33 * 16)          // resident A splits 0,1; padded stride 33 chunks
#define BOFF       (ARES_BYTES)                 // 135168
#define BBUF_BYTES (2 * 128 * 9 * 16)           // B double buffer; padded stride 9 chunks
#define MVOFF      (BOFF + BBUF_BYTES)          // 172032: merge values 128 f32
#define MJOFF      (MVOFF + 512)
#define SMEM_TOTAL (MJOFF + 512)                // 173056

__device__ __forceinline__ void ldsm4(uint32_t* r, uint32_t saddr) {
    asm volatile("ldmatrix.sync.aligned.m8n8.x4.shared.b16 {%0,%1,%2,%3}, [%4];"
                 : "=r"(r[0]), "=r"(r[1]), "=r"(r[2]), "=r"(r[3]) : "r"(saddr));
}
__device__ __forceinline__ void mma16816(float (&d)[4], const uint32_t (&a)[4],
                                         uint32_t b0, uint32_t b1) {
    asm volatile(
        "mma.sync.aligned.m16n8k16.row.col.f32.f16.f16.f32 "
        "{%0,%1,%2,%3},{%4,%5,%6,%7},{%8,%9},{%0,%1,%2,%3};"
        : "+f"(d[0]), "+f"(d[1]), "+f"(d[2]), "+f"(d[3])
        : "r"(a[0]), "r"(a[1]), "r"(a[2]), "r"(a[3]), "r"(b0), "r"(b1));
}

__device__ __forceinline__ void loadB_regs(uint4* r, const __half* xsb,
                                           int j0, int sb, int kc, int tid) {
#pragma unroll
    for (int q = 0; q < 4; ++q) {
        int idx = tid + q * 256;
        int row = idx >> 3, ch = idx & 7;
        r[q] = *(const uint4*)(xsb + (size_t)(j0 + row) * 512 + sb * 256 + kc * 64 + ch * 8);
    }
}
__device__ __forceinline__ void storeB_smem(char* sm, const uint4* r, int buf, int tid) {
#pragma unroll
    for (int q = 0; q < 4; ++q) {
        int idx = tid + q * 256;
        int row = idx >> 3, ch = idx & 7;
        *(uint4*)(sm + BOFF + ((((buf << 7) + row) * 9 + ch) << 4)) = r[q];
    }
}

// ---------------------------------------------------------------------------
// simargmax: emulated-fp32 GEMM via 3 fp16 split pairs {(0,0),(1,0),(0,1)}
// + fused argmax. grid (16, BB), 256 threads = 8 warps (4 M x 2 N).
// ---------------------------------------------------------------------------
__global__ __launch_bounds__(256, 1) void simargmax_kernel() {
    extern __shared__ __align__(1024) char sm[];
    const int b = blockIdx.y, i0 = blockIdx.x * 128;
    const int tid = threadIdx.x, lane = tid & 31, wid = tid >> 5;
    const int wm = wid >> 1, wn = wid & 1;
    const uint32_t smb = (uint32_t)__cvta_generic_to_shared(sm);
    const __half* xsb = g_xs + (size_t)b * NN * 512;

    // resident A: both splits, rows i0..i0+127, full K=256 (32 chunks/row)
#pragma unroll
    for (int r = 0; r < 32; ++r) {
        int idx = tid + r * 256;            // 8192 chunks
        int s   = idx >> 12;
        int row = (idx >> 5) & 127;
        int ch  = idx & 31;
        uint4 v = *(const uint4*)(xsb + (size_t)(i0 + row) * 512 + s * 256 + ch * 8);
        *(uint4*)(sm + ((((s << 7) + row) * 33 + ch) << 4)) = v;
    }

    const int ar0 = wm * 32 + (lane & 15);          // A ldmatrix row (+ mt*16)
    const int akh = lane >> 4;                      // A k-half chunk
    const int jr0 = wn * 64 + ((lane >> 4) & 1) * 8 + (lane & 7);  // B row (+ ntp*16)
    const int bkh = (lane >> 3) & 1;                // B k-half chunk

    const float NEG = __int_as_float(0xff800000);
    float best[4]; int bidx[4];
#pragma unroll
    for (int s = 0; s < 4; ++s) { best[s] = NEG; bidx[s] = 0; }

    for (int jt = 0; jt < 16; ++jt) {
        const int j0 = jt * 128;
        float acc[2][8][4];
#pragma unroll
        for (int mt = 0; mt < 2; ++mt)
#pragma unroll
            for (int nt = 0; nt < 8; ++nt)
#pragma unroll
                for (int rr = 0; rr < 4; ++rr) acc[mt][nt][rr] = 0.f;

        uint4 breg[4];
        loadB_regs(breg, xsb, j0, 0, 0, tid);
        storeB_smem(sm, breg, 0, tid);    // safe: last reader of buf0 synced last it
        __syncthreads();

        // 8 B tiles per jt: it = sb*4 + kc. sb=0 pairs with A splits {0,1};
        // sb=1 pairs with A split {0} only.
        for (int it = 0; it < 8; ++it) {
            const int buf = it & 1;
            const int kc = it & 3;
            const int nq = (it < 4) ? 2 : 1;     // #A splits for this B split
            const int itn = it + 1;
            const bool hn = itn < 8;
            if (hn) loadB_regs(breg, xsb, j0, itn >> 2, itn & 3, tid);

#pragma unroll
            for (int ks = 0; ks < 4; ++ks) {
                uint32_t bf[4][4];
#pragma unroll
                for (int ntp = 0; ntp < 4; ++ntp) {
                    uint32_t bd = smb + BOFF +
                        (((((buf << 7) + jr0 + ntp * 16) * 9) + ks * 2 + bkh) << 4);
                    ldsm4(bf[ntp], bd);
                }
                for (int q = 0; q < nq; ++q) {
                    uint32_t a[2][4];
                    const int cb = kc * 8 + ks * 2;
#pragma unroll
                    for (int mt = 0; mt < 2; ++mt) {
                        uint32_t ad = smb + (((((q << 7) + ar0 + mt * 16) * 33) + cb + akh) << 4);
                        ldsm4(a[mt], ad);
                    }
#pragma unroll
                    for (int ntp = 0; ntp < 4; ++ntp) {
                        mma16816(acc[0][ntp * 2],     a[0], bf[ntp][0], bf[ntp][1]);
                        mma16816(acc[0][ntp * 2 + 1], a[0], bf[ntp][2], bf[ntp][3]);
                        mma16816(acc[1][ntp * 2],     a[1], bf[ntp][0], bf[ntp][1]);
                        mma16816(acc[1][ntp * 2 + 1], a[1], bf[ntp][2], bf[ntp][3]);
                    }
                }
            }
            // store next tile into the other buffer: its last reader finished
            // before the barrier at the end of the previous iteration.
            if (hn) storeB_smem(sm, breg, buf ^ 1, tid);
            __syncthreads();
        }

        // epilogue: mask diagonal, running argmax (j monotonic -> '>' keeps first)
#pragma unroll
        for (int mt = 0; mt < 2; ++mt)
#pragma unroll
            for (int nt = 0; nt < 8; ++nt)
#pragma unroll
                for (int rr = 0; rr < 4; ++rr) {
                    int jl = wn * 64 + nt * 8 + (lane & 3) * 2 + (rr & 1);
                    int il = wm * 32 + mt * 16 + (rr >> 1) * 8 + (lane >> 2);
                    float v = acc[mt][nt][rr];
                    if (j0 + jl == i0 + il) v = NEG;
                    int slot = mt * 2 + (rr >> 1);
                    if (v > best[slot]) { best[slot] = v; bidx[slot] = j0 + jl; }
                }
    }

    // cross-lane (quad) + cross-warp_n reduction; first-index tie-break
    float* Rv = (float*)(sm + MVOFF);
    int*   Rj = (int*)(sm + MJOFF);
#pragma unroll
    for (int slot = 0; slot < 4; ++slot) {
        float v = best[slot]; int j = bidx[slot];
#pragma unroll
        for (int o = 1; o <= 2; o <<= 1) {
            float vo = __shfl_xor_sync(0xffffffffu, v, o);
            int   jo = __shfl_xor_sync(0xffffffffu, j, o);
            if (vo > v || (vo == v && jo < j)) { v = vo; j = jo; }
        }
        best[slot] = v; bidx[slot] = j;
        int row = wm * 32 + (slot >> 1) * 16 + (slot & 1) * 8 + (lane >> 2);
        if (wn == 1 && (lane & 3) == 0) { Rv[row] = v; Rj[row] = j; }
    }
    __syncthreads();
    if (wn == 0 && (lane & 3) == 0) {
#pragma unroll
        for (int slot = 0; slot < 4; ++slot) {
            int row = wm * 32 + (slot >> 1) * 16 + (slot & 1) * 8 + (lane >> 2);
            float v = best[slot]; int j = bidx[slot];
            float vo = Rv[row]; int jo = Rj[row];
            if (vo > v || (vo == v && jo < j)) { v = vo; j = jo; }
            g_idx[b * NN + i0 + row] = j;
        }
    }
}

// ---------------------------------------------------------------------------
// fuse: staged in smem via g_xt; coalesced reads/writes. grid (NN/32, BB), 256 thr.
// ---------------------------------------------------------------------------
#define FS_SF 32896
#define FS_W  65792
#define FS_JI 69888
#define FS_W0 70016
#define FS_W1 70144
#define FS_TOTAL 70272

__global__ __launch_bounds__(256) void fuse_kernel(const float* __restrict__ W,
                                                   float* __restrict__ out) {
    extern __shared__ char fsm[];
    float* Sx  = (float*)fsm;               // [32][257]
    float* Sf  = (float*)(fsm + FS_SF);     // [32][257]
    float* Wsh = (float*)(fsm + FS_W);      // [1024]
    int*   Ji  = (int*)(fsm + FS_JI);
    float* W0  = (float*)(fsm + FS_W0);
    float* W1  = (float*)(fsm + FS_W1);

    int b = blockIdx.y, n0 = blockIdx.x * 32, tid = threadIdx.x;
    for (int e = tid; e < 1024; e += 256) Wsh[e] = W[e];
    if (tid < 32) Ji[tid] = g_idx[b * NN + n0 + tid];
    __syncthreads();

    const float* xtb = g_xt + (size_t)b * NN * 256;
    {
        int r = tid >> 3, p = tid & 7;
        const float* srcx = xtb + (size_t)(n0 + r) * 256 + p * 32;
        const float* srcf = xtb + (size_t)Ji[r] * 256 + p * 32;
#pragma unroll
        for (int q = 0; q < 8; ++q) {
            float4 a = *(const float4*)(srcx + q * 4);
            float4 c = *(const float4*)(srcf + q * 4);
            int cb = p * 32 + q * 4;
            Sx[r * 257 + cb] = a.x; Sx[r * 257 + cb + 1] = a.y;
            Sx[r * 257 + cb + 2] = a.z; Sx[r * 257 + cb + 3] = a.w;
            Sf[r * 257 + cb] = c.x; Sf[r * 257 + cb + 1] = c.y;
            Sf[r * 257 + cb + 2] = c.z; Sf[r * 257 + cb + 3] = c.w;
        }
    }
    __syncthreads();
    {
        int r = tid >> 3, p = tid & 7;
        float l0 = 0.f, l1 = 0.f;
#pragma unroll
        for (int cc = 0; cc < 32; ++cc) {
            int c = p * 32 + cc;
            float xv = Sx[r * 257 + c], fv = Sf[r * 257 + c];
            l0 = fmaf(xv, Wsh[c], fmaf(fv, Wsh[256 + c], l0));
            l1 = fmaf(xv, Wsh[512 + c], fmaf(fv, Wsh[768 + c], l1));
        }
#pragma unroll
        for (int o = 4; o; o >>= 1) {
            l0 += __shfl_down_sync(0xffffffffu, l0, o, 8);
            l1 += __shfl_down_sync(0xffffffffu, l1, o, 8);
        }
        if (p == 0) {
            float m = fmaxf(l0, l1);
            float e0 = expf(l0 - m), e1 = expf(l1 - m);
            float inv = 1.f / (e0 + e1);
            W0[r] = e0 * inv; W1[r] = e1 * inv;
        }
    }
    __syncthreads();
    {
        int nl = tid & 31, cg = tid >> 5;
        float w0 = W0[nl], w1 = W1[nl];
        float* o0 = out + (size_t)b * CC * NN;
        float* o1 = out + (size_t)BB * CC * NN + (size_t)b * CC * NN;
#pragma unroll
        for (int cc = 0; cc < 32; ++cc) {
            int c = cg * 32 + cc;
            float xv = Sx[nl * 257 + c], fv = Sf[nl * 257 + c];
            o0[(size_t)c * NN + n0 + nl] = fmaf(xv, w0, fv * w1);
            o1[(size_t)c * NN + n0 + nl] = fv;
        }
    }
}

// ---------------------------------------------------------------------------
extern "C" void kernel_launch(void* const* d_in, const int* in_sizes, int n_in,
                              void* d_out, int out_size) {
    const float* x = (const float*)d_in[0];
    const float* W = (const float*)d_in[1];
    float* out = (float*)d_out;

    cudaFuncSetAttribute(simargmax_kernel,
                         cudaFuncAttributeMaxDynamicSharedMemorySize, SMEM_TOTAL);
    cudaFuncSetAttribute(fuse_kernel,
                         cudaFuncAttributeMaxDynamicSharedMemorySize, FS_TOTAL);

    prep_kernel<<<dim3(NN / 32, BB), 256>>>(x);
    simargmax_kernel<<<dim3(16, BB), 256, SMEM_TOTAL>>>();
    fuse_kernel<<<dim3(NN / 32, BB), 256, FS_TOTAL>>>(W, out);
}